// round 3
// baseline (speedup 1.0000x reference)
#include <cuda_runtime.h>
#include <math.h>

#define BATCH  4
#define S      160
#define S4     40                 // S/4 vec4 per row
#define SLICE4 (S * S4)           // 6400 vec4 per (b,d) slice
#define NSLICE (BATCH * S)        // 640
#define NWORD  5                  // 160 bits = 5 u32 words
#define MAIN_X 5
#define NPART  (MAIN_X * NSLICE)  // 3200 partials
#define NTOT   (4LL * 160 * 160 * 160)

// ---- device scratch (zero-init at load; last blocks reset for replay) ----
__device__ unsigned g_bm[BATCH][3][NWORD];   // [b][ax: D,H,W][word], atomicOr target
__device__ int      g_cnt1;                  // proj ticket counter
__device__ int      g_cnt2;                  // main ticket counter
__device__ int      g_lo[BATCH][3];
__device__ int      g_hi[BATCH][3];
__device__ int      g_hasfg[BATCH];
__device__ float    g_part[NPART];           // overwritten unconditionally each run

// ---------------------------------------------------------------------------
// Kernel 1: mask projection + (in last block) bbox bounds.
// One block per (b,d) slice; 256 threads x 25 int4 = whole slice.
__global__ void __launch_bounds__(256) proj_kernel(const int4* __restrict__ mask) {
    __shared__ unsigned char sH[S];
    __shared__ unsigned char sW[S];
    __shared__ int sAny;
    __shared__ int sLast;
    int t  = threadIdx.x;
    int bz = blockIdx.x;                  // 0..639
    int b  = bz / S;
    int d  = bz - b * S;

    if (t < S) { sH[t] = 0; sW[t] = 0; }
    if (t == 0) sAny = 0;
    __syncthreads();

    const size_t base = (size_t)bz * SLICE4;
    bool any = false;
    #pragma unroll
    for (int it = 0; it < 25; it++) {
        int pos = it * 256 + t;           // 0..6399
        int h   = pos / S4;
        int w   = (pos - h * S4) * 4;
        int4 v  = mask[base + pos];
        bool a0 = v.x > 0, a1 = v.y > 0, a2 = v.z > 0, a3 = v.w > 0;
        if (a0) sW[w + 0] = 1;
        if (a1) sW[w + 1] = 1;
        if (a2) sW[w + 2] = 1;
        if (a3) sW[w + 3] = 1;
        if (a0 | a1 | a2 | a3) { sH[h] = 1; any = true; }
    }
    if (any) sAny = 1;                    // benign shared race
    __syncthreads();

    // Publish packed bitmaps: threads 0..4 -> H, 5..9 -> W, 10 -> D bit.
    if (t < 2 * NWORD) {
        int wi = (t < NWORD) ? t : t - NWORD;
        const unsigned char* src = (t < NWORD) ? sH : sW;
        unsigned word = 0;
        #pragma unroll
        for (int k = 0; k < 32; k++)
            word |= ((unsigned)src[wi * 32 + k]) << k;
        if (word) atomicOr(&g_bm[b][(t < NWORD) ? 1 : 2][wi], word);
    } else if (t == 2 * NWORD) {
        if (sAny) atomicOr(&g_bm[b][0][d >> 5], 1u << (d & 31));
    }

    // Last-block election
    __threadfence();
    __syncthreads();
    if (t == 0) {
        int ticket = atomicAdd(&g_cnt1, 1);
        sLast = (ticket == NSLICE - 1);
    }
    __syncthreads();
    if (!sLast) return;

    // Last block: compute bounds for 12 (batch, axis) pairs, then reset state.
    if (t < BATCH * 3) {
        int bb = t / 3;
        int ax = t - bb * 3;
        volatile unsigned* bm = g_bm[bb][ax];

        int mn = -1, mx = -1;
        #pragma unroll
        for (int wi = 0; wi < NWORD; wi++) {
            unsigned v = bm[wi];
            if (v) {
                if (mn < 0) mn = wi * 32 + (__ffs(v) - 1);
                mx = wi * 32 + (31 - __clz(v));
            }
        }
        int lo = 0, hi = 0, fg = 0;
        if (mn >= 0) {
            fg = 1;
            float fm = (float)mn, fM = (float)mx;
            float c = (fM + fm) * 0.5f;
            float e = ((fM - fm + 1.0f) * 0.5f) * 1.2f;      // reference assoc.
            lo = (int)fmaxf(0.0f, floorf(c - e));
            hi = (int)fminf((float)(S - 1), floorf(c + e));  // EXCLUSIVE end
        }
        g_lo[bb][ax] = lo;
        g_hi[bb][ax] = hi;
        if (ax == 0) g_hasfg[bb] = fg;
    }
    // reset bitmaps + counter for the next (deterministic) replay
    if (t < BATCH * 3 * NWORD) (&g_bm[0][0][0])[t] = 0;
    if (t == 0) g_cnt1 = 0;
}

// ---------------------------------------------------------------------------
// Kernel 2: weighted MSE + (in last block) final reduction.
// 3200 blocks x 256 threads; block k covers slice k/5, sub-range k%5.
__global__ void __launch_bounds__(256) main_kernel(const float4* __restrict__ p,
                                                   const float4* __restrict__ q,
                                                   float* __restrict__ out) {
    __shared__ float warp_part[8];
    __shared__ int sLast;
    int t   = threadIdx.x;
    int blk = blockIdx.x;                 // 0..3199
    int bz  = blk / MAIN_X;               // slice 0..639
    int sub = blk - bz * MAIN_X;          // 0..4
    int b   = bz / S;
    int d   = bz - b * S;

    int fg  = g_hasfg[b];
    int loD = g_lo[b][0], hiD = g_hi[b][0];
    int loH = g_lo[b][1], hiH = g_hi[b][1];
    int loW = g_lo[b][2], hiW = g_hi[b][2];
    bool inD = fg && (d >= loD) && (d < hiD);

    const size_t base = (size_t)bz * SLICE4;
    float sum = 0.0f;

    #pragma unroll
    for (int it = 0; it < 5; it++) {
        int pos = (sub + it * MAIN_X) * 256 + t;   // covers 0..6399 over 5 subs
        int h   = pos / S4;
        int w   = (pos - h * S4) * 4;
        float4 a = p[base + pos];
        float4 c = q[base + pos];
        bool inHD = inD && (h >= loH) && (h < hiH);
        float w0 = (inHD && (w + 0 >= loW) && (w + 0 < hiW)) ? 1.0f : 0.1f;
        float w1 = (inHD && (w + 1 >= loW) && (w + 1 < hiW)) ? 1.0f : 0.1f;
        float w2 = (inHD && (w + 2 >= loW) && (w + 2 < hiW)) ? 1.0f : 0.1f;
        float w3 = (inHD && (w + 3 >= loW) && (w + 3 < hiW)) ? 1.0f : 0.1f;
        float d0 = w0 * a.x - w0 * c.x;    // mirror roi*pred - roi*true
        float d1 = w1 * a.y - w1 * c.y;
        float d2 = w2 * a.z - w2 * c.z;
        float d3 = w3 * a.w - w3 * c.w;
        sum = fmaf(d0, d0, sum);
        sum = fmaf(d1, d1, sum);
        sum = fmaf(d2, d2, sum);
        sum = fmaf(d3, d3, sum);
    }

    // block reduce -> one disjoint partial
    #pragma unroll
    for (int o = 16; o > 0; o >>= 1)
        sum += __shfl_down_sync(0xFFFFFFFFu, sum, o);
    int lane = t & 31, wid = t >> 5;
    if (lane == 0) warp_part[wid] = sum;
    __syncthreads();
    if (wid == 0) {
        float v = (lane < 8) ? warp_part[lane] : 0.0f;
        #pragma unroll
        for (int o = 4; o > 0; o >>= 1)
            v += __shfl_down_sync(0xFFFFFFFFu, v, o);
        if (lane == 0) g_part[blk] = v;
    }

    // last-block election + final reduction
    __threadfence();
    __syncthreads();
    if (t == 0) {
        int ticket = atomicAdd(&g_cnt2, 1);
        sLast = (ticket == NPART - 1);
    }
    __syncthreads();
    if (!sLast) return;

    double acc = 0.0;
    for (int i = t; i < NPART; i += 256)
        acc += (double)__ldcg(&g_part[i]);

    __shared__ double dwarp[8];
    #pragma unroll
    for (int o = 16; o > 0; o >>= 1)
        acc += __shfl_down_sync(0xFFFFFFFFu, acc, o);
    if (lane == 0) dwarp[wid] = acc;
    __syncthreads();
    if (wid == 0) {
        double v = (lane < 8) ? dwarp[lane] : 0.0;
        #pragma unroll
        for (int o = 4; o > 0; o >>= 1)
            v += __shfl_down_sync(0xFFFFFFFFu, v, o);
        if (lane == 0) {
            out[0] = (float)(v / (double)NTOT);
            g_cnt2 = 0;                    // reset for deterministic replay
        }
    }
}

// ---------------------------------------------------------------------------
extern "C" void kernel_launch(void* const* d_in, const int* in_sizes, int n_in,
                              void* d_out, int out_size) {
    const float4* y_pred = (const float4*)d_in[0];
    const float4* y_true = (const float4*)d_in[1];
    const int4*   mask   = (const int4*)d_in[2];
    float* out = (float*)d_out;

    proj_kernel<<<NSLICE, 256>>>(mask);
    main_kernel<<<NPART, 256>>>(y_pred, y_true, out);
}